// round 6
// baseline (speedup 1.0000x reference)
#include <cuda_runtime.h>

#define SPOS   110592      // 48*48*48
#define CCH    96
#define NWINS  512
#define NTOK   216
#define NHEADS 4
#define HD     24
#define TBL    1331        // 11*11*11

// Scratch (allocation-free: __device__ globals). pos-major [pos][c] layout.
__device__ float g_q[SPOS * CCH];
__device__ float g_k[SPOS * CCH];
__device__ float g_v[SPOS * CCH];
__device__ float g_o[SPOS * CCH];

// ---------------------------------------------------------------------------
// Fast exp2 on the FMA/ALU pipes (no MUFU). Input in log2 domain.
// |rel err| ~1e-7 over the useful range; clamps at -126 so masked scores
// underflow to ~1e-38 (softmax-correct).
// ---------------------------------------------------------------------------
__device__ __forceinline__ float exp2_fast(float s)
{
    s = fmaxf(s, -126.0f);
    float t = s + 12582912.0f;                 // 1.5*2^23: round-to-nearest int
    int   n = __float_as_int(t) - 0x4B400000;  // n = round(s)
    float r = s - (t - 12582912.0f);           // r in [-0.5, 0.5]
    float p =            1.33336498e-3f;
    p = fmaf(p, r, 9.61804694e-3f);
    p = fmaf(p, r, 5.55042563e-2f);
    p = fmaf(p, r, 2.40226507e-1f);
    p = fmaf(p, r, 6.93147182e-1f);
    p = fmaf(p, r, 1.00000000e+0f);
    return __int_as_float(__float_as_int(p) + (n << 23));
}

// ---------------------------------------------------------------------------
// proj_in: y[pos][o] = sum_ci x[ci][pos] * W[o][ci] + b[o]
// ---------------------------------------------------------------------------
#define SMEM_PI ((96*97 + 96*128 + 96) * 4)

__global__ __launch_bounds__(512, 2) void proj_in_kernel(
    const float* __restrict__ x, const float* __restrict__ W,
    const float* __restrict__ b, float* __restrict__ y)
{
    extern __shared__ float sm[];
    float* ws = sm;               // [o][ci] stride 97
    float* xs = ws + 96 * 97;     // [ci][p] stride 128
    float* bs = xs + 96 * 128;    // 96
    const int tid = threadIdx.x;
    const int p0 = blockIdx.x * 128;

    for (int i = tid; i < 96 * 96; i += 512) {
        int o = i / 96, ci = i - o * 96;
        ws[o * 97 + ci] = W[i];
    }
    if (tid < 96) bs[tid] = b[tid];
    for (int i = tid; i < 96 * 128; i += 512) {
        int ci = i >> 7, p = i & 127;
        xs[i] = x[ci * SPOS + p0 + p];
    }
    __syncthreads();

    const int lane = tid & 31, wp = tid >> 5;   // wp 0..15
    const int pl = wp * 8;
    const int o0 = lane * 3;

    float acc[8][3];
#pragma unroll
    for (int p = 0; p < 8; p++)
#pragma unroll
        for (int k = 0; k < 3; k++) acc[p][k] = 0.f;

    for (int ci = 0; ci < 96; ci++) {
        float4 xa = *reinterpret_cast<const float4*>(&xs[ci * 128 + pl]);
        float4 xb = *reinterpret_cast<const float4*>(&xs[ci * 128 + pl + 4]);
        float w0 = ws[(o0 + 0) * 97 + ci];
        float w1 = ws[(o0 + 1) * 97 + ci];
        float w2 = ws[(o0 + 2) * 97 + ci];
        float xr[8] = {xa.x, xa.y, xa.z, xa.w, xb.x, xb.y, xb.z, xb.w};
#pragma unroll
        for (int p = 0; p < 8; p++) {
            acc[p][0] += xr[p] * w0;
            acc[p][1] += xr[p] * w1;
            acc[p][2] += xr[p] * w2;
        }
    }

    float b0 = bs[o0], b1 = bs[o0 + 1], b2 = bs[o0 + 2];
#pragma unroll
    for (int p = 0; p < 8; p++) {
        float* yp = &y[(size_t)(p0 + pl + p) * 96 + o0];
        yp[0] = acc[p][0] + b0;
        yp[1] = acc[p][1] + b1;
        yp[2] = acc[p][2] + b2;
    }
}

// ---------------------------------------------------------------------------
// attn: one block per (window, head). 128 threads.
// Threads 0..95 own rows (t, t+96)  [2-row path: K/V LDS amortized 2x].
// Threads 96..119 own row (96 + t)  [1-row tail path, rows 192..215].
// All arithmetic in log2 domain; exp2 on FMA pipe (no MUFU floor).
// ---------------------------------------------------------------------------
#define SMEM_AT ((NTOK*HD*2 + TBL) * 4 + (NTOK * 3) * 4)

__global__ __launch_bounds__(128, 3) void attn_kernel(
    const float* __restrict__ rel_table, const int* __restrict__ use_shift)
{
    extern __shared__ float sm[];
    float* ks    = sm;                  // 216*24
    float* vs    = ks + NTOK * HD;      // 216*24
    float* biasL = vs + NTOK * HD;      // 1331 (pre-scaled by log2e)
    int*   ppos  = (int*)(biasL + TBL); // 216
    int*   regid = ppos + NTOK;         // 216
    int*   joff  = regid + NTOK;        // 216

    const int tid = threadIdx.x;
    const int win = blockIdx.x, h = blockIdx.y;
    const int shift = (*use_shift) ? 3 : 0;
    const float LOG2E = 1.44269504f;

    for (int i = tid; i < NTOK; i += 128) {
        int td = i / 36;
        int r  = i - td * 36;
        int th = r / 6;
        int tw = r - th * 6;
        int gd = (win >> 6) * 6 + td;
        int gh = ((win >> 3) & 7) * 6 + th;
        int gw = (win & 7) * 6 + tw;
        int od = gd + shift; if (od >= 48) od -= 48;
        int oh = gh + shift; if (oh >= 48) oh -= 48;
        int ow = gw + shift; if (ow >= 48) ow -= 48;
        ppos[i] = (od * 48 + oh) * 48 + ow;
        int rd = (gd < 42) ? 0 : ((gd < 45) ? 1 : 2);
        int rh = (gh < 42) ? 0 : ((gh < 45) ? 1 : 2);
        int rw = (gw < 42) ? 0 : ((gw < 45) ? 1 : 2);
        regid[i] = (rd * 3 + rh) * 3 + rw;
        joff[i]  = td * 121 + th * 11 + tw;
    }
    for (int i = tid; i < TBL; i += 128)
        biasL[i] = rel_table[i * NHEADS + h] * LOG2E;
    __syncthreads();

    for (int e = tid; e < NTOK * HD; e += 128) {
        int rrow = e / HD;
        int d    = e - rrow * HD;
        int base = ppos[rrow] * 96 + h * HD + d;
        ks[e] = g_k[base];
        vs[e] = g_v[base];
    }
    __syncthreads();

    const float SCL2 = 0.2041241452319315f * 1.44269504088896f; // scale*log2e
    const float mval = shift ? -144.269504f : 0.0f;              // -100*log2e

    if (tid < 96) {
        // ---- two-row path: rows tid, tid+96 ----
        const int r0 = tid, r1 = tid + 96;
        const int base0 = ppos[r0] * 96 + h * HD;
        const int base1 = ppos[r1] * 96 + h * HD;

        float qa[HD], qb[HD];
#pragma unroll
        for (int t = 0; t < 6; t++) {
            float4 qq = *reinterpret_cast<const float4*>(&g_q[base0 + 4 * t]);
            qa[4*t]   = qq.x * SCL2;  qa[4*t+1] = qq.y * SCL2;
            qa[4*t+2] = qq.z * SCL2;  qa[4*t+3] = qq.w * SCL2;
        }
#pragma unroll
        for (int t = 0; t < 6; t++) {
            float4 qq = *reinterpret_cast<const float4*>(&g_q[base1 + 4 * t]);
            qb[4*t]   = qq.x * SCL2;  qb[4*t+1] = qq.y * SCL2;
            qb[4*t+2] = qq.z * SCL2;  qb[4*t+3] = qq.w * SCL2;
        }

        const int ibase0 = joff[r0] + 665;
        const int ibase1 = joff[r1] + 665;
        const int ri0 = regid[r0], ri1 = regid[r1];

        float la = 0.f, lb = 0.f;
        float acca[HD], accb[HD];
#pragma unroll
        for (int d = 0; d < HD; d++) { acca[d] = 0.f; accb[d] = 0.f; }

        for (int j = 0; j < NTOK; j++) {
            const float4* kr = reinterpret_cast<const float4*>(&ks[j * HD]);
            const int jo = joff[j];
            const int rj = regid[j];
            float sa = biasL[ibase0 - jo];
            float sb = biasL[ibase1 - jo];
            float sa1 = 0.f, sb1 = 0.f;
#pragma unroll
            for (int t = 0; t < 6; t++) {
                float4 kk = kr[t];
                sa  += qa[4*t]   * kk.x + qa[4*t+2] * kk.z;
                sa1 += qa[4*t+1] * kk.y + qa[4*t+3] * kk.w;
                sb  += qb[4*t]   * kk.x + qb[4*t+2] * kk.z;
                sb1 += qb[4*t+1] * kk.y + qb[4*t+3] * kk.w;
            }
            float ssa = sa + sa1;
            float ssb = sb + sb1;
            if (rj != ri0) ssa += mval;
            if (rj != ri1) ssb += mval;
            float pa = exp2_fast(ssa);
            float pb = exp2_fast(ssb);
            la += pa;
            lb += pb;
            const float4* vr = reinterpret_cast<const float4*>(&vs[j * HD]);
#pragma unroll
            for (int t = 0; t < 6; t++) {
                float4 vv = vr[t];
                acca[4*t]   += pa * vv.x;  acca[4*t+1] += pa * vv.y;
                acca[4*t+2] += pa * vv.z;  acca[4*t+3] += pa * vv.w;
                accb[4*t]   += pb * vv.x;  accb[4*t+1] += pb * vv.y;
                accb[4*t+2] += pb * vv.z;  accb[4*t+3] += pb * vv.w;
            }
        }

        float inva = 1.f / la;
        float invb = 1.f / lb;
#pragma unroll
        for (int t = 0; t < 6; t++) {
            float4 r;
            r.x = acca[4*t]   * inva;  r.y = acca[4*t+1] * inva;
            r.z = acca[4*t+2] * inva;  r.w = acca[4*t+3] * inva;
            *reinterpret_cast<float4*>(&g_o[base0 + 4 * t]) = r;
        }
#pragma unroll
        for (int t = 0; t < 6; t++) {
            float4 r;
            r.x = accb[4*t]   * invb;  r.y = accb[4*t+1] * invb;
            r.z = accb[4*t+2] * invb;  r.w = accb[4*t+3] * invb;
            *reinterpret_cast<float4*>(&g_o[base1 + 4 * t]) = r;
        }
    } else if (tid < 120) {
        // ---- one-row tail path: rows 192..215 ----
        const int r0 = 96 + tid;          // 192..215
        const int base0 = ppos[r0] * 96 + h * HD;

        float qa[HD];
#pragma unroll
        for (int t = 0; t < 6; t++) {
            float4 qq = *reinterpret_cast<const float4*>(&g_q[base0 + 4 * t]);
            qa[4*t]   = qq.x * SCL2;  qa[4*t+1] = qq.y * SCL2;
            qa[4*t+2] = qq.z * SCL2;  qa[4*t+3] = qq.w * SCL2;
        }
        const int ibase0 = joff[r0] + 665;
        const int ri0 = regid[r0];

        float la = 0.f;
        float acca[HD];
#pragma unroll
        for (int d = 0; d < HD; d++) acca[d] = 0.f;

        for (int j = 0; j < NTOK; j++) {
            const float4* kr = reinterpret_cast<const float4*>(&ks[j * HD]);
            float sa = biasL[ibase0 - joff[j]];
            float sa1 = 0.f;
#pragma unroll
            for (int t = 0; t < 6; t++) {
                float4 kk = kr[t];
                sa  += qa[4*t]   * kk.x + qa[4*t+2] * kk.z;
                sa1 += qa[4*t+1] * kk.y + qa[4*t+3] * kk.w;
            }
            float ssa = sa + sa1;
            if (regid[j] != ri0) ssa += mval;
            float pa = exp2_fast(ssa);
            la += pa;
            const float4* vr = reinterpret_cast<const float4*>(&vs[j * HD]);
#pragma unroll
            for (int t = 0; t < 6; t++) {
                float4 vv = vr[t];
                acca[4*t]   += pa * vv.x;  acca[4*t+1] += pa * vv.y;
                acca[4*t+2] += pa * vv.z;  acca[4*t+3] += pa * vv.w;
            }
        }

        float inva = 1.f / la;
#pragma unroll
        for (int t = 0; t < 6; t++) {
            float4 r;
            r.x = acca[4*t]   * inva;  r.y = acca[4*t+1] * inva;
            r.z = acca[4*t+2] * inva;  r.w = acca[4*t+3] * inva;
            *reinterpret_cast<float4*>(&g_o[base0 + 4 * t]) = r;
        }
    }
}

// ---------------------------------------------------------------------------
// proj_out: out[o][pos] = sum_ci x[pos][ci] * W[o][ci] + b[o]
// ---------------------------------------------------------------------------
#define SMEM_PO ((96*97 + 96*132 + 96) * 4)

__global__ __launch_bounds__(512, 2) void proj_out_kernel(
    const float* __restrict__ xpm, const float* __restrict__ W,
    const float* __restrict__ b, float* __restrict__ y)
{
    extern __shared__ float sm[];
    float* ws = sm;               // [o][ci] stride 97
    float* xs = ws + 96 * 97;     // [ci][p] stride 132 (float4-aligned)
    float* bs = xs + 96 * 132;
    const int tid = threadIdx.x;
    const int p0 = blockIdx.x * 128;

    for (int i = tid; i < 96 * 96; i += 512) {
        int o = i / 96, ci = i - o * 96;
        ws[o * 97 + ci] = W[i];
    }
    if (tid < 96) bs[tid] = b[tid];
    for (int i = tid; i < 128 * 96; i += 512) {
        int p = i / 96, ci = i - p * 96;
        xs[ci * 132 + p] = xpm[(size_t)(p0 + p) * 96 + ci];
    }
    __syncthreads();

    const int lane = tid & 31, wg = tid >> 5;  // wg 0..15
    const int pl = lane * 4;
    const int o0 = wg * 6;

    float acc[4][6];
#pragma unroll
    for (int p = 0; p < 4; p++)
#pragma unroll
        for (int k = 0; k < 6; k++) acc[p][k] = 0.f;

    for (int ci = 0; ci < 96; ci++) {
        float4 xa = *reinterpret_cast<const float4*>(&xs[ci * 132 + pl]);
        float xr[4] = {xa.x, xa.y, xa.z, xa.w};
        float wv[6];
#pragma unroll
        for (int k = 0; k < 6; k++) wv[k] = ws[(o0 + k) * 97 + ci];
#pragma unroll
        for (int p = 0; p < 4; p++)
#pragma unroll
            for (int k = 0; k < 6; k++) acc[p][k] += xr[p] * wv[k];
    }

#pragma unroll
    for (int k = 0; k < 6; k++) {
        int o = o0 + k;
        float bb = bs[o];
        float4 r;
        r.x = acc[0][k] + bb;  r.y = acc[1][k] + bb;
        r.z = acc[2][k] + bb;  r.w = acc[3][k] + bb;
        *reinterpret_cast<float4*>(&y[(size_t)o * SPOS + p0 + pl]) = r;
    }
}

// ---------------------------------------------------------------------------

extern "C" void kernel_launch(void* const* d_in, const int* in_sizes, int n_in,
                              void* d_out, int out_size)
{
    const float* q_in = (const float*)d_in[0];
    const float* k_in = (const float*)d_in[1];
    const float* v_in = (const float*)d_in[2];
    const float* Wq   = (const float*)d_in[3];
    const float* bq   = (const float*)d_in[4];
    const float* Wk   = (const float*)d_in[5];
    const float* bk   = (const float*)d_in[6];
    const float* Wv   = (const float*)d_in[7];
    const float* bv   = (const float*)d_in[8];
    const float* Wp   = (const float*)d_in[9];
    const float* bp   = (const float*)d_in[10];
    const float* rel  = (const float*)d_in[11];
    const int*   ush  = (const int*)d_in[12];
    float* out = (float*)d_out;

    float *gq, *gk, *gv, *go;
    cudaGetSymbolAddress((void**)&gq, g_q);
    cudaGetSymbolAddress((void**)&gk, g_k);
    cudaGetSymbolAddress((void**)&gv, g_v);
    cudaGetSymbolAddress((void**)&go, g_o);

    cudaFuncSetAttribute(proj_in_kernel,
        cudaFuncAttributeMaxDynamicSharedMemorySize, SMEM_PI);
    cudaFuncSetAttribute(attn_kernel,
        cudaFuncAttributeMaxDynamicSharedMemorySize, SMEM_AT);
    cudaFuncSetAttribute(proj_out_kernel,
        cudaFuncAttributeMaxDynamicSharedMemorySize, SMEM_PO);

    const int grid = SPOS / 128;  // 864
    proj_in_kernel<<<grid, 512, SMEM_PI>>>(q_in, Wq, bq, gq);
    proj_in_kernel<<<grid, 512, SMEM_PI>>>(k_in, Wk, bk, gk);
    proj_in_kernel<<<grid, 512, SMEM_PI>>>(v_in, Wv, bv, gv);
    attn_kernel<<<dim3(NWINS, NHEADS), 128, SMEM_AT>>>(rel, ush);
    proj_out_kernel<<<grid, 512, SMEM_PO>>>(go, Wp, bp, out);
}

// round 7
// speedup vs baseline: 1.6718x; 1.6718x over previous
#include <cuda_runtime.h>

#define SPOS   110592      // 48*48*48
#define CCH    96
#define NWINS  512
#define NTOK   216
#define NHEADS 4
#define HD     24
#define TBL    1331        // 11*11*11

// Scratch (allocation-free: __device__ globals). pos-major [pos][c] layout.
__device__ float g_q[SPOS * CCH];
__device__ float g_k[SPOS * CCH];
__device__ float g_v[SPOS * CCH];
__device__ float g_o[SPOS * CCH];

// ---------------------------------------------------------------------------
// tf32 helpers (3xTF32 decomposition for fp32-accurate tensor-core GEMM)
// ---------------------------------------------------------------------------
__device__ __forceinline__ unsigned cvt_tf32(float x) {
    unsigned r;
    asm("cvt.rna.tf32.f32 %0, %1;" : "=r"(r) : "f"(x));
    return r;
}
__device__ __forceinline__ void split_tf32(float x, unsigned& hi, unsigned& lo) {
    hi = cvt_tf32(x);
    lo = cvt_tf32(x - __uint_as_float(hi));
}
__device__ __forceinline__ void mma_tf32(
    float& d0, float& d1, float& d2, float& d3,
    unsigned a0, unsigned a1, unsigned a2, unsigned a3,
    unsigned b0, unsigned b1)
{
    asm("mma.sync.aligned.m16n8k8.row.col.f32.tf32.tf32.f32 "
        "{%0,%1,%2,%3}, {%4,%5,%6,%7}, {%8,%9}, {%0,%1,%2,%3};"
        : "+f"(d0), "+f"(d1), "+f"(d2), "+f"(d3)
        : "r"(a0), "r"(a1), "r"(a2), "r"(a3), "r"(b0), "r"(b1));
}

// ---------------------------------------------------------------------------
// proj_in (tensor-core): y[pos][o] = sum_ci x[ci][pos] * W[o][ci] + b[o]
// x channel-major [c][SPOS]; y pos-major [pos][96].
// Block: 128 pos x 96 out; 16 warps = 8 m-tiles(16 pos) x 2 n-halves(48 out).
// smem: W [o][ci] stride 100, X [ci][p] stride 136 (conflict-free gathers).
// ---------------------------------------------------------------------------
#define XS_STRIDE_I 136
#define WS_STRIDE   100
#define SMEM_PI ((96*WS_STRIDE + 96*XS_STRIDE_I + 96) * 4)

__global__ __launch_bounds__(512, 2) void proj_in_tc_kernel(
    const float* __restrict__ x, const float* __restrict__ W,
    const float* __restrict__ b, float* __restrict__ y)
{
    extern __shared__ float sm[];
    float* ws = sm;                        // [o][ci] stride 100
    float* xs = ws + 96 * WS_STRIDE;       // [ci][p] stride 136
    float* bs = xs + 96 * XS_STRIDE_I;     // 96
    const int tid = threadIdx.x;
    const int p0 = blockIdx.x * 128;

    for (int i = tid; i < 96 * 96; i += 512) {
        int o = i / 96, ci = i - o * 96;
        ws[o * WS_STRIDE + ci] = W[i];
    }
    if (tid < 96) bs[tid] = b[tid];
    for (int i = tid; i < 96 * 128; i += 512) {
        int ci = i >> 7, p = i & 127;
        xs[ci * XS_STRIDE_I + p] = x[ci * SPOS + p0 + p];
    }
    __syncthreads();

    const int lane = tid & 31;
    const int wid  = tid >> 5;
    const int mw   = wid & 7;        // 0..7 -> pos tile
    const int nw   = wid >> 3;       // 0..1 -> out half
    const int g    = lane >> 2;      // 0..7
    const int tg   = lane & 3;       // 0..3
    const int pb   = mw * 16;

    float acc[6][4];
#pragma unroll
    for (int t = 0; t < 6; t++)
#pragma unroll
        for (int r = 0; r < 4; r++) acc[t][r] = 0.f;

    for (int k0 = 0; k0 < 96; k0 += 8) {
        unsigned ah[4], al[4];
        split_tf32(xs[(k0 + tg)     * XS_STRIDE_I + pb + g],     ah[0], al[0]);
        split_tf32(xs[(k0 + tg)     * XS_STRIDE_I + pb + g + 8], ah[1], al[1]);
        split_tf32(xs[(k0 + tg + 4) * XS_STRIDE_I + pb + g],     ah[2], al[2]);
        split_tf32(xs[(k0 + tg + 4) * XS_STRIDE_I + pb + g + 8], ah[3], al[3]);
#pragma unroll
        for (int t = 0; t < 6; t++) {
            int n0 = nw * 48 + t * 8;
            unsigned bh0, bl0, bh1, bl1;
            split_tf32(ws[(n0 + g) * WS_STRIDE + k0 + tg],     bh0, bl0);
            split_tf32(ws[(n0 + g) * WS_STRIDE + k0 + tg + 4], bh1, bl1);
            mma_tf32(acc[t][0], acc[t][1], acc[t][2], acc[t][3],
                     ah[0], ah[1], ah[2], ah[3], bh0, bh1);
            mma_tf32(acc[t][0], acc[t][1], acc[t][2], acc[t][3],
                     ah[0], ah[1], ah[2], ah[3], bl0, bl1);
            mma_tf32(acc[t][0], acc[t][1], acc[t][2], acc[t][3],
                     al[0], al[1], al[2], al[3], bh0, bh1);
        }
    }

    const int r0 = p0 + pb + g;
#pragma unroll
    for (int t = 0; t < 6; t++) {
        int o = nw * 48 + t * 8 + 2 * tg;
        float b0 = bs[o], b1 = bs[o + 1];
        float2 v0 = make_float2(acc[t][0] + b0, acc[t][1] + b1);
        float2 v1 = make_float2(acc[t][2] + b0, acc[t][3] + b1);
        *reinterpret_cast<float2*>(&y[(size_t)r0 * 96 + o])       = v0;
        *reinterpret_cast<float2*>(&y[(size_t)(r0 + 8) * 96 + o]) = v1;
    }
}

// ---------------------------------------------------------------------------
// proj_out (tensor-core): out[o][pos] = sum_ci xpm[pos][ci] * W[o][ci] + b[o]
// xpm pos-major [pos][96]; out channel-major [o][SPOS].
// ---------------------------------------------------------------------------
#define XS_STRIDE_O 137
#define SMEM_PO ((96*WS_STRIDE + 96*XS_STRIDE_O + 96) * 4)

__global__ __launch_bounds__(512, 2) void proj_out_tc_kernel(
    const float* __restrict__ xpm, const float* __restrict__ W,
    const float* __restrict__ b, float* __restrict__ y)
{
    extern __shared__ float sm[];
    float* ws = sm;                        // [o][ci] stride 100
    float* xs = ws + 96 * WS_STRIDE;       // [ci][p] stride 137
    float* bs = xs + 96 * XS_STRIDE_O;
    const int tid = threadIdx.x;
    const int p0 = blockIdx.x * 128;

    for (int i = tid; i < 96 * 96; i += 512) {
        int o = i / 96, ci = i - o * 96;
        ws[o * WS_STRIDE + ci] = W[i];
    }
    if (tid < 96) bs[tid] = b[tid];
    for (int i = tid; i < 128 * 96; i += 512) {
        int p = i / 96, ci = i - p * 96;
        xs[ci * XS_STRIDE_O + p] = xpm[(size_t)(p0 + p) * 96 + ci];
    }
    __syncthreads();

    const int lane = tid & 31;
    const int wid  = tid >> 5;
    const int mw   = wid & 7;
    const int nw   = wid >> 3;
    const int g    = lane >> 2;
    const int tg   = lane & 3;
    const int pb   = mw * 16;

    float acc[6][4];
#pragma unroll
    for (int t = 0; t < 6; t++)
#pragma unroll
        for (int r = 0; r < 4; r++) acc[t][r] = 0.f;

    for (int k0 = 0; k0 < 96; k0 += 8) {
        unsigned ah[4], al[4];
        split_tf32(xs[(k0 + tg)     * XS_STRIDE_O + pb + g],     ah[0], al[0]);
        split_tf32(xs[(k0 + tg)     * XS_STRIDE_O + pb + g + 8], ah[1], al[1]);
        split_tf32(xs[(k0 + tg + 4) * XS_STRIDE_O + pb + g],     ah[2], al[2]);
        split_tf32(xs[(k0 + tg + 4) * XS_STRIDE_O + pb + g + 8], ah[3], al[3]);
#pragma unroll
        for (int t = 0; t < 6; t++) {
            int n0 = nw * 48 + t * 8;
            unsigned bh0, bl0, bh1, bl1;
            split_tf32(ws[(n0 + g) * WS_STRIDE + k0 + tg],     bh0, bl0);
            split_tf32(ws[(n0 + g) * WS_STRIDE + k0 + tg + 4], bh1, bl1);
            mma_tf32(acc[t][0], acc[t][1], acc[t][2], acc[t][3],
                     ah[0], ah[1], ah[2], ah[3], bh0, bh1);
            mma_tf32(acc[t][0], acc[t][1], acc[t][2], acc[t][3],
                     ah[0], ah[1], ah[2], ah[3], bl0, bl1);
            mma_tf32(acc[t][0], acc[t][1], acc[t][2], acc[t][3],
                     al[0], al[1], al[2], al[3], bh0, bh1);
        }
    }

    const int r0 = p0 + pb + g;
#pragma unroll
    for (int t = 0; t < 6; t++) {
        int o = nw * 48 + t * 8 + 2 * tg;
        float b0 = bs[o], b1 = bs[o + 1];
        y[(size_t)o * SPOS + r0]           = acc[t][0] + b0;
        y[(size_t)(o + 1) * SPOS + r0]     = acc[t][1] + b1;
        y[(size_t)o * SPOS + r0 + 8]       = acc[t][2] + b0;
        y[(size_t)(o + 1) * SPOS + r0 + 8] = acc[t][3] + b1;
    }
}

// ---------------------------------------------------------------------------
// attn: one block per (window, head). 224 threads, rows 0..215 active.
// (R4 version verbatim — best measured: 383us.)
// ---------------------------------------------------------------------------
#define SMEM_AT ((NTOK*HD*2 + TBL) * 4 + (NTOK * 3) * 4)

__global__ __launch_bounds__(224, 3) void attn_kernel(
    const float* __restrict__ rel_table, const int* __restrict__ use_shift)
{
    extern __shared__ float sm[];
    float* ks    = sm;                  // 216*24
    float* vs    = ks + NTOK * HD;      // 216*24
    float* biasL = vs + NTOK * HD;      // 1331
    int*   ppos  = (int*)(biasL + TBL); // 216
    int*   regid = ppos + NTOK;         // 216
    int*   joff  = regid + NTOK;        // 216

    const int tid = threadIdx.x;
    const int win = blockIdx.x, h = blockIdx.y;
    const int shift = (*use_shift) ? 3 : 0;

    if (tid < NTOK) {
        int td = tid / 36;
        int r  = tid - td * 36;
        int th = r / 6;
        int tw = r - th * 6;
        int gd = (win >> 6) * 6 + td;
        int gh = ((win >> 3) & 7) * 6 + th;
        int gw = (win & 7) * 6 + tw;
        int od = gd + shift; if (od >= 48) od -= 48;
        int oh = gh + shift; if (oh >= 48) oh -= 48;
        int ow = gw + shift; if (ow >= 48) ow -= 48;
        ppos[tid] = (od * 48 + oh) * 48 + ow;
        int rd = (gd < 42) ? 0 : ((gd < 45) ? 1 : 2);
        int rh = (gh < 42) ? 0 : ((gh < 45) ? 1 : 2);
        int rw = (gw < 42) ? 0 : ((gw < 45) ? 1 : 2);
        regid[tid] = (rd * 3 + rh) * 3 + rw;
        joff[tid]  = td * 121 + th * 11 + tw;
    }
    for (int i = tid; i < TBL; i += 224) biasL[i] = rel_table[i * NHEADS + h];
    __syncthreads();

    for (int e = tid; e < NTOK * HD; e += 224) {
        int rrow = e / HD;
        int d    = e - rrow * HD;
        int base = ppos[rrow] * 96 + h * HD + d;
        ks[e] = g_k[base];
        vs[e] = g_v[base];
    }
    __syncthreads();

    if (tid < NTOK) {
        const float SCL = 0.2041241452319315f;  // 24^-0.5
        float q[HD];
        const int base = ppos[tid] * 96 + h * HD;
#pragma unroll
        for (int t = 0; t < 6; t++) {
            float4 qq = *reinterpret_cast<const float4*>(&g_q[base + 4 * t]);
            q[4*t]   = qq.x * SCL;  q[4*t+1] = qq.y * SCL;
            q[4*t+2] = qq.z * SCL;  q[4*t+3] = qq.w * SCL;
        }
        const int ibase = joff[tid] + 665;   // (+5)*121 + (+5)*11 + (+5)
        const int ri = regid[tid];
        const float mval = shift ? -100.0f : 0.0f;

        float l = 0.f;
        float acc[HD];
#pragma unroll
        for (int d = 0; d < HD; d++) acc[d] = 0.f;

#pragma unroll 2
        for (int j = 0; j < NTOK; j++) {
            const float4* kr = reinterpret_cast<const float4*>(&ks[j * HD]);
            float s0 = biasL[ibase - joff[j]];
            float s1 = 0.f, s2 = 0.f, s3 = 0.f;
#pragma unroll
            for (int t = 0; t < 6; t++) {
                float4 kk = kr[t];
                s0 += q[4*t]   * kk.x;
                s1 += q[4*t+1] * kk.y;
                s2 += q[4*t+2] * kk.z;
                s3 += q[4*t+3] * kk.w;
            }
            float s = (s0 + s1) + (s2 + s3);
            if (regid[j] != ri) s += mval;
            float p = __expf(s);
            l += p;
            const float4* vr = reinterpret_cast<const float4*>(&vs[j * HD]);
#pragma unroll
            for (int t = 0; t < 6; t++) {
                float4 vv = vr[t];
                acc[4*t]   += p * vv.x;  acc[4*t+1] += p * vv.y;
                acc[4*t+2] += p * vv.z;  acc[4*t+3] += p * vv.w;
            }
        }

        float inv = 1.f / l;
#pragma unroll
        for (int t = 0; t < 6; t++) {
            float4 r;
            r.x = acc[4*t]   * inv;  r.y = acc[4*t+1] * inv;
            r.z = acc[4*t+2] * inv;  r.w = acc[4*t+3] * inv;
            *reinterpret_cast<float4*>(&g_o[base + 4 * t]) = r;
        }
    }
}

// ---------------------------------------------------------------------------

extern "C" void kernel_launch(void* const* d_in, const int* in_sizes, int n_in,
                              void* d_out, int out_size)
{
    const float* q_in = (const float*)d_in[0];
    const float* k_in = (const float*)d_in[1];
    const float* v_in = (const float*)d_in[2];
    const float* Wq   = (const float*)d_in[3];
    const float* bq   = (const float*)d_in[4];
    const float* Wk   = (const float*)d_in[5];
    const float* bk   = (const float*)d_in[6];
    const float* Wv   = (const float*)d_in[7];
    const float* bv   = (const float*)d_in[8];
    const float* Wp   = (const float*)d_in[9];
    const float* bp   = (const float*)d_in[10];
    const float* rel  = (const float*)d_in[11];
    const int*   ush  = (const int*)d_in[12];
    float* out = (float*)d_out;

    float *gq, *gk, *gv, *go;
    cudaGetSymbolAddress((void**)&gq, g_q);
    cudaGetSymbolAddress((void**)&gk, g_k);
    cudaGetSymbolAddress((void**)&gv, g_v);
    cudaGetSymbolAddress((void**)&go, g_o);

    cudaFuncSetAttribute(proj_in_tc_kernel,
        cudaFuncAttributeMaxDynamicSharedMemorySize, SMEM_PI);
    cudaFuncSetAttribute(attn_kernel,
        cudaFuncAttributeMaxDynamicSharedMemorySize, SMEM_AT);
    cudaFuncSetAttribute(proj_out_tc_kernel,
        cudaFuncAttributeMaxDynamicSharedMemorySize, SMEM_PO);

    const int grid = SPOS / 128;  // 864
    proj_in_tc_kernel<<<grid, 512, SMEM_PI>>>(q_in, Wq, bq, gq);
    proj_in_tc_kernel<<<grid, 512, SMEM_PI>>>(k_in, Wk, bk, gk);
    proj_in_tc_kernel<<<grid, 512, SMEM_PI>>>(v_in, Wv, bv, gv);
    attn_kernel<<<dim3(NWINS, NHEADS), 224, SMEM_AT>>>(rel, ush);
    proj_out_tc_kernel<<<grid, 512, SMEM_PO>>>(go, Wp, bp, out);
}